// round 3
// baseline (speedup 1.0000x reference)
#include <cuda_runtime.h>
#include <cstdint>

// Problem constants
#define NB 2
#define NS 2048
#define ND 1024
#define NH 16
#define NDH 64
#define NM (NB * NS)

// Scratch (device globals: allocation-free)
__device__ float g_q[(size_t)NB * NH * NS * NDH];
__device__ float g_k[(size_t)NB * NH * NS * NDH];
__device__ float g_v[(size_t)NB * NH * NS * NDH];
__device__ float g_attn[(size_t)NB * NS * ND];
__device__ float g_rowsum[(size_t)NB * NH * NS];

// ---------------- tf32 mma helpers ----------------
__device__ __forceinline__ uint32_t f2tf(float f) {
    uint32_t u;
    asm("cvt.rna.tf32.f32 %0, %1;" : "=r"(u) : "f"(f));
    return u;
}
__device__ __forceinline__ float uaf(uint32_t u) { return __uint_as_float(u); }
__device__ __forceinline__ uint32_t fau(float f) { return __float_as_uint(f); }

__device__ __forceinline__ void mma_tf32(float c[4], const uint32_t a[4], const uint32_t b[2]) {
    asm volatile(
        "mma.sync.aligned.m16n8k8.row.col.f32.tf32.tf32.f32 "
        "{%0,%1,%2,%3}, {%4,%5,%6,%7}, {%8,%9}, {%0,%1,%2,%3};"
        : "+f"(c[0]), "+f"(c[1]), "+f"(c[2]), "+f"(c[3])
        : "r"(a[0]), "r"(a[1]), "r"(a[2]), "r"(a[3]), "r"(b[0]), "r"(b[1]));
}

// ---------------------------------------------------------------------------
// Batched GEMM: C = A @ W^T + bias, tf32, double-buffered smem.
// M=4096, N=K=1024. BM=BN=128, BK=16, 256 threads, warp tile 32x64.
// SPLIT=1: out (b,h,s,dh), 3 problems via blockIdx.z; SPLIT=0: row-major.
// ---------------------------------------------------------------------------
#define GS 20
struct G3 {
    const float* A[3];
    const float* W[3];
    const float* B[3];
    float* O[3];
};

template <int SPLIT>
__global__ __launch_bounds__(256) void gemm_tf32(G3 p)
{
    __shared__ float As[2][128 * GS];
    __shared__ float Ws[2][128 * GS];

    const int z = SPLIT ? blockIdx.z : 0;
    const float* __restrict__ A = p.A[z];
    const float* __restrict__ W = p.W[z];
    const float* __restrict__ bias = p.B[z];
    float* __restrict__ out = p.O[z];

    const int tid = threadIdx.x;
    const int wid = tid >> 5, lane = tid & 31;
    const int g = lane >> 2, t = lane & 3;
    const int wm = (wid & 3) * 32;
    const int wn = (wid >> 2) * 64;
    const int bm = blockIdx.y * 128, bn = blockIdx.x * 128;

    const int lr = tid >> 1;
    const int lk = (tid & 1) * 8;

    float c[2][8][4];
#pragma unroll
    for (int i = 0; i < 2; i++)
#pragma unroll
        for (int j = 0; j < 8; j++)
#pragma unroll
            for (int q = 0; q < 4; q++) c[i][j][q] = 0.f;

    const float* aptr = A + (size_t)(bm + lr) * ND + lk;
    const float* wptr = W + (size_t)(bn + lr) * ND + lk;

    // Prologue: stage k0=0
    {
        float4 a0 = *(const float4*)(aptr);
        float4 a1 = *(const float4*)(aptr + 4);
        float4 w0 = *(const float4*)(wptr);
        float4 w1 = *(const float4*)(wptr + 4);
        *(float4*)&As[0][lr * GS + lk]     = make_float4(uaf(f2tf(a0.x)), uaf(f2tf(a0.y)), uaf(f2tf(a0.z)), uaf(f2tf(a0.w)));
        *(float4*)&As[0][lr * GS + lk + 4] = make_float4(uaf(f2tf(a1.x)), uaf(f2tf(a1.y)), uaf(f2tf(a1.z)), uaf(f2tf(a1.w)));
        *(float4*)&Ws[0][lr * GS + lk]     = make_float4(uaf(f2tf(w0.x)), uaf(f2tf(w0.y)), uaf(f2tf(w0.z)), uaf(f2tf(w0.w)));
        *(float4*)&Ws[0][lr * GS + lk + 4] = make_float4(uaf(f2tf(w1.x)), uaf(f2tf(w1.y)), uaf(f2tf(w1.z)), uaf(f2tf(w1.w)));
    }
    __syncthreads();

    for (int k0 = 0; k0 < ND; k0 += 16) {
        const int s = (k0 >> 4) & 1;
        const bool more = (k0 + 16) < ND;
        float4 a0, a1, w0, w1;
        if (more) {
            a0 = *(const float4*)(aptr + k0 + 16);
            a1 = *(const float4*)(aptr + k0 + 20);
            w0 = *(const float4*)(wptr + k0 + 16);
            w1 = *(const float4*)(wptr + k0 + 20);
        }

#pragma unroll
        for (int kk = 0; kk < 16; kk += 8) {
            uint32_t af[2][4];
#pragma unroll
            for (int mt = 0; mt < 2; mt++) {
                const int r = wm + mt * 16;
                af[mt][0] = fau(As[s][(r + g)     * GS + kk + t]);
                af[mt][1] = fau(As[s][(r + g + 8) * GS + kk + t]);
                af[mt][2] = fau(As[s][(r + g)     * GS + kk + t + 4]);
                af[mt][3] = fau(As[s][(r + g + 8) * GS + kk + t + 4]);
            }
#pragma unroll
            for (int nt = 0; nt < 8; nt++) {
                uint32_t bf[2];
                const int col = wn + nt * 8;
                bf[0] = fau(Ws[s][(col + g) * GS + kk + t]);
                bf[1] = fau(Ws[s][(col + g) * GS + kk + t + 4]);
                mma_tf32(c[0][nt], af[0], bf);
                mma_tf32(c[1][nt], af[1], bf);
            }
        }

        if (more) {
            const int d = s ^ 1;
            *(float4*)&As[d][lr * GS + lk]     = make_float4(uaf(f2tf(a0.x)), uaf(f2tf(a0.y)), uaf(f2tf(a0.z)), uaf(f2tf(a0.w)));
            *(float4*)&As[d][lr * GS + lk + 4] = make_float4(uaf(f2tf(a1.x)), uaf(f2tf(a1.y)), uaf(f2tf(a1.z)), uaf(f2tf(a1.w)));
            *(float4*)&Ws[d][lr * GS + lk]     = make_float4(uaf(f2tf(w0.x)), uaf(f2tf(w0.y)), uaf(f2tf(w0.z)), uaf(f2tf(w0.w)));
            *(float4*)&Ws[d][lr * GS + lk + 4] = make_float4(uaf(f2tf(w1.x)), uaf(f2tf(w1.y)), uaf(f2tf(w1.z)), uaf(f2tf(w1.w)));
            __syncthreads();
        }
    }

#pragma unroll
    for (int mt = 0; mt < 2; mt++) {
#pragma unroll
        for (int rr = 0; rr < 2; rr++) {
            const int m = bm + wm + mt * 16 + g + rr * 8;
            const int b = m >> 11, sIdx = m & (NS - 1);
#pragma unroll
            for (int nt = 0; nt < 8; nt++) {
                const int col = bn + wn + nt * 8 + 2 * t;
                float2 v;
                v.x = c[mt][nt][rr * 2 + 0] + bias[col];
                v.y = c[mt][nt][rr * 2 + 1] + bias[col + 1];
                if (SPLIT) {
                    const int h = col >> 6, dh = col & 63;
                    *(float2*)&out[((size_t)(b * NH + h) * NS + sIdx) * NDH + dh] = v;
                } else {
                    *(float2*)&out[(size_t)m * ND + col] = v;
                }
            }
        }
    }
}

// ---------------------------------------------------------------------------
// Attention v3: block = 128 q rows, 256 threads (8 warps, 4m x 2n).
// Warp tile 32q x 32keys (mt=2, nt=4). Q fragments register-resident (64 regs)
// -> S-phase needs only 1 LDS per mma. S-tile processed in two nt-halves to
// bound register pressure. E goes through smem (aliases Q staging buffer).
// Dynamic smem: E/Q 128x68, K 64x68, V 64x72, red 256  (= 71,680 B).
// ---------------------------------------------------------------------------
__global__ __launch_bounds__(256) void attn_tf32(
    const int* __restrict__ mask, float* __restrict__ wout)
{
    extern __shared__ float dsm[];
    float* Es  = dsm;                    // 128*68 (Q staging, then E)
    float* Ks  = dsm + 128 * 68;         // 64*68
    float* Vs  = Ks + 64 * 68;           // 64*72
    float* red = Vs + 64 * 72;           // 256

    const int b = blockIdx.z, h = blockIdx.y;
    const int q0 = blockIdx.x * 128;
    const int tid = threadIdx.x;
    const int wid = tid >> 5, lane = tid & 31;
    const int g = lane >> 2, t = lane & 3;
    const int wm = (wid & 3) * 32;       // q rows within block
    const int wn = (wid >> 2) * 32;      // key cols (S) / dh cols (PV)
    const size_t bh = (size_t)(b * NH + h);

    // Stage Q (128x64) into Es, tf32-converted
    const float* qptr = g_q + (bh * NS + q0) * NDH;
#pragma unroll
    for (int i = 0; i < 8; i++) {
        const int lin = tid + i * 256;
        const int r = lin >> 4, c4 = (lin & 15) * 4;
        float4 v = *(const float4*)(qptr + r * NDH + c4);
        *(float4*)&Es[r * 68 + c4] =
            make_float4(uaf(f2tf(v.x)), uaf(f2tf(v.y)), uaf(f2tf(v.z)), uaf(f2tf(v.w)));
    }
    __syncthreads();

    // Q fragments: 2 m-tiles x 8 k-chunks x 4 regs = 64 registers
    uint32_t qf[2][8][4];
#pragma unroll
    for (int mt = 0; mt < 2; mt++) {
        const int r0 = (wm + mt * 16 + g) * 68;
        const int r1 = (wm + mt * 16 + g + 8) * 68;
#pragma unroll
        for (int kk = 0; kk < 8; kk++) {
            qf[mt][kk][0] = fau(Es[r0 + kk * 8 + t]);
            qf[mt][kk][1] = fau(Es[r1 + kk * 8 + t]);
            qf[mt][kk][2] = fau(Es[r0 + kk * 8 + t + 4]);
            qf[mt][kk][3] = fau(Es[r1 + kk * 8 + t + 4]);
        }
    }

    float cacc[2][4][4];
#pragma unroll
    for (int mt = 0; mt < 2; mt++)
#pragma unroll
        for (int nt = 0; nt < 4; nt++)
#pragma unroll
            for (int q = 0; q < 4; q++) cacc[mt][nt][q] = 0.f;
    float rs[2][2] = {{0.f, 0.f}, {0.f, 0.f}};

    const int* mbase = mask + (size_t)b * NS * NS;
    float* wbase = wout ? wout + bh * NS * NS : nullptr;

    for (int kt = 0; kt < NS / 64; kt++) {
        __syncthreads();   // prev PV reads of Es/Ks/Vs done (also covers qf build)
        const float* kptr = g_k + (bh * NS + kt * 64) * NDH;
        const float* vptr = g_v + (bh * NS + kt * 64) * NDH;
#pragma unroll
        for (int i = 0; i < 4; i++) {
            const int lin = tid + i * 256;
            const int r = lin >> 4, c4 = (lin & 15) * 4;
            float4 kv = *(const float4*)(kptr + r * NDH + c4);
            float4 vv = *(const float4*)(vptr + r * NDH + c4);
            *(float4*)&Ks[r * 68 + c4] =
                make_float4(uaf(f2tf(kv.x)), uaf(f2tf(kv.y)), uaf(f2tf(kv.z)), uaf(f2tf(kv.w)));
            *(float4*)&Vs[r * 72 + c4] =
                make_float4(uaf(f2tf(vv.x)), uaf(f2tf(vv.y)), uaf(f2tf(vv.z)), uaf(f2tf(vv.w)));
        }
        __syncthreads();

        // S-phase in two nt-halves (keeps lg live range at 16 regs)
#pragma unroll
        for (int nh = 0; nh < 2; nh++) {
            float lg[2][2][4];
#pragma unroll
            for (int mt = 0; mt < 2; mt++)
#pragma unroll
                for (int n2 = 0; n2 < 2; n2++)
#pragma unroll
                    for (int q = 0; q < 4; q++) lg[mt][n2][q] = 0.f;

#pragma unroll
            for (int kk = 0; kk < 8; kk++) {
#pragma unroll
                for (int n2 = 0; n2 < 2; n2++) {
                    const int kc = wn + (nh * 2 + n2) * 8;
                    uint32_t bf[2];
                    bf[0] = fau(Ks[(kc + g) * 68 + kk * 8 + t]);
                    bf[1] = fau(Ks[(kc + g) * 68 + kk * 8 + t + 4]);
                    mma_tf32(lg[0][n2], qf[0][kk], bf);
                    mma_tf32(lg[1][n2], qf[1][kk], bf);
                }
            }

            // mask + exp + unnormalized weight write + rowsum; E into smem (tf32)
#pragma unroll
            for (int mt = 0; mt < 2; mt++) {
                const int qr0 = q0 + wm + mt * 16 + g;
                const int qr1 = qr0 + 8;
#pragma unroll
                for (int n2 = 0; n2 < 2; n2++) {
                    const int klocal = wn + (nh * 2 + n2) * 8 + 2 * t;
                    const int kcg = kt * 64 + klocal;
                    int2 m0 = *(const int2*)(mbase + (size_t)qr0 * NS + kcg);
                    int2 m1 = *(const int2*)(mbase + (size_t)qr1 * NS + kcg);
                    float e0 = m0.x ? 0.f : __expf(lg[mt][n2][0] * 0.125f);
                    float e1 = m0.y ? 0.f : __expf(lg[mt][n2][1] * 0.125f);
                    float e2 = m1.x ? 0.f : __expf(lg[mt][n2][2] * 0.125f);
                    float e3 = m1.y ? 0.f : __expf(lg[mt][n2][3] * 0.125f);
                    rs[mt][0] += e0 + e1;
                    rs[mt][1] += e2 + e3;
                    if (wbase) {
                        *(float2*)&wbase[(size_t)qr0 * NS + kcg] = make_float2(e0, e1);
                        *(float2*)&wbase[(size_t)qr1 * NS + kcg] = make_float2(e2, e3);
                    }
                    // E to smem (safe: prev PV reads fenced by top-of-loop sync)
                    const int er0 = (wm + mt * 16 + g) * 68 + klocal;
                    const int er1 = (wm + mt * 16 + g + 8) * 68 + klocal;
                    *(float2*)&Es[er0] = make_float2(uaf(f2tf(e0)), uaf(f2tf(e1)));
                    *(float2*)&Es[er1] = make_float2(uaf(f2tf(e2)), uaf(f2tf(e3)));
                }
            }
        }
        __syncthreads();   // all E tiles visible

        // PV: cacc += E(128x64) @ V(64x64), warp tile 32q x 32dh
#pragma unroll
        for (int kk = 0; kk < 8; kk++) {
            uint32_t af[2][4];
#pragma unroll
            for (int mt = 0; mt < 2; mt++) {
                const int r0 = (wm + mt * 16 + g) * 68;
                const int r1 = (wm + mt * 16 + g + 8) * 68;
                af[mt][0] = fau(Es[r0 + kk * 8 + t]);
                af[mt][1] = fau(Es[r1 + kk * 8 + t]);
                af[mt][2] = fau(Es[r0 + kk * 8 + t + 4]);
                af[mt][3] = fau(Es[r1 + kk * 8 + t + 4]);
            }
#pragma unroll
            for (int nt = 0; nt < 4; nt++) {
                const int dc = wn + nt * 8 + g;
                uint32_t bf[2];
                bf[0] = fau(Vs[(kk * 8 + t)     * 72 + dc]);
                bf[1] = fau(Vs[(kk * 8 + t + 4) * 72 + dc]);
                mma_tf32(cacc[0][nt], af[0], bf);
                mma_tf32(cacc[1][nt], af[1], bf);
            }
        }
    }

    // Rowsums: quad-reduce over t, then across the 2 n-warps via smem
#pragma unroll
    for (int mt = 0; mt < 2; mt++) {
#pragma unroll
        for (int hlf = 0; hlf < 2; hlf++) {
            rs[mt][hlf] += __shfl_xor_sync(0xffffffffu, rs[mt][hlf], 1);
            rs[mt][hlf] += __shfl_xor_sync(0xffffffffu, rs[mt][hlf], 2);
        }
    }
    __syncthreads();
    if (t == 0) {
        const int half = (wid >> 2) * 128;
#pragma unroll
        for (int mt = 0; mt < 2; mt++) {
            red[half + wm + mt * 16 + g]     = rs[mt][0];
            red[half + wm + mt * 16 + g + 8] = rs[mt][1];
        }
    }
    __syncthreads();

#pragma unroll
    for (int mt = 0; mt < 2; mt++) {
        const int row0 = wm + mt * 16 + g;
        const int row1 = row0 + 8;
        const float tot0 = red[row0] + red[128 + row0];
        const float tot1 = red[row1] + red[128 + row1];
        if (wn == 0 && t == 0) {
            g_rowsum[bh * NS + q0 + row0] = tot0;
            g_rowsum[bh * NS + q0 + row1] = tot1;
        }
        const float inv0 = 1.f / tot0, inv1 = 1.f / tot1;
#pragma unroll
        for (int nt = 0; nt < 4; nt++) {
            const int dh = wn + nt * 8 + 2 * t;
            *(float2*)&g_attn[((size_t)b * NS + q0 + row0) * ND + h * NDH + dh] =
                make_float2(cacc[mt][nt][0] * inv0, cacc[mt][nt][1] * inv0);
            *(float2*)&g_attn[((size_t)b * NS + q0 + row1) * ND + h * NDH + dh] =
                make_float2(cacc[mt][nt][2] * inv1, cacc[mt][nt][3] * inv1);
        }
    }
}

// Scale each weights row by 1/rowsum
__global__ __launch_bounds__(128) void norm_w(float* __restrict__ w)
{
    const int row = blockIdx.x;
    const float inv = 1.f / g_rowsum[row];
    float4* p = (float4*)(w + (size_t)row * NS);
#pragma unroll
    for (int i = threadIdx.x; i < NS / 4; i += 128) {
        float4 v = p[i];
        v.x *= inv; v.y *= inv; v.z *= inv; v.w *= inv;
        p[i] = v;
    }
}

extern "C" void kernel_launch(void* const* d_in, const int* in_sizes, int n_in,
                              void* d_out, int out_size)
{
    const float* Xq  = (const float*)d_in[0];
    const float* Xk  = (const float*)d_in[1];
    const float* Xv  = (const float*)d_in[2];
    const int*   msk = (const int*)d_in[3];
    const float* Wq  = (const float*)d_in[4];
    const float* bq  = (const float*)d_in[5];
    const float* Wk  = (const float*)d_in[6];
    const float* bk  = (const float*)d_in[7];
    const float* Wv  = (const float*)d_in[8];
    const float* bv  = (const float*)d_in[9];
    const float* Wo  = (const float*)d_in[10];
    const float* bo  = (const float*)d_in[11];

    float* out = (float*)d_out;
    const size_t n_attn = (size_t)NB * NS * ND;
    const size_t n_w    = (size_t)NB * NH * NS * NS;

    float* attn_dst = nullptr;
    float* w_dst = nullptr;
    if ((size_t)out_size >= n_attn + n_w) { attn_dst = out; w_dst = out + n_attn; }
    else if ((size_t)out_size >= n_w)     { w_dst = out; }
    else                                  { attn_dst = out; }

    float *pq, *pk, *pv, *pa;
    cudaGetSymbolAddress((void**)&pq, g_q);
    cudaGetSymbolAddress((void**)&pk, g_k);
    cudaGetSymbolAddress((void**)&pv, g_v);
    cudaGetSymbolAddress((void**)&pa, g_attn);

    // Batched Q/K/V projections
    G3 pj;
    pj.A[0] = Xq; pj.W[0] = Wq; pj.B[0] = bq; pj.O[0] = pq;
    pj.A[1] = Xk; pj.W[1] = Wk; pj.B[1] = bk; pj.O[1] = pk;
    pj.A[2] = Xv; pj.W[2] = Wv; pj.B[2] = bv; pj.O[2] = pv;
    gemm_tf32<1><<<dim3(ND / 128, NM / 128, 3), 256>>>(pj);

    // Attention (dynamic smem 71,680 B)
    const int attn_smem = (128 * 68 + 64 * 68 + 64 * 72 + 256) * 4;
    cudaFuncSetAttribute(attn_tf32, cudaFuncAttributeMaxDynamicSharedMemorySize, attn_smem);
    attn_tf32<<<dim3(NS / 128, NH, NB), 256, attn_smem>>>(msk, w_dst);

    if (w_dst) norm_w<<<NB * NH * NS, 128>>>(w_dst);

    if (attn_dst) {
        G3 po;
        po.A[0] = pa; po.W[0] = Wo; po.B[0] = bo; po.O[0] = attn_dst;
        po.A[1] = pa; po.W[1] = Wo; po.B[1] = bo; po.O[1] = attn_dst;
        po.A[2] = pa; po.W[2] = Wo; po.B[2] = bo; po.O[2] = attn_dst;
        gemm_tf32<0><<<dim3(ND / 128, NM / 128, 1), 256>>>(po);
    }
}

// round 4
// speedup vs baseline: 1.0024x; 1.0024x over previous
#include <cuda_runtime.h>
#include <cstdint>

// Problem constants
#define NB 2
#define NS 2048
#define ND 1024
#define NH 16
#define NDH 64
#define NM (NB * NS)

// Scratch (device globals: allocation-free)
__device__ float g_q[(size_t)NB * NH * NS * NDH];
__device__ float g_k[(size_t)NB * NH * NS * NDH];
__device__ float g_v[(size_t)NB * NH * NS * NDH];
__device__ float g_attn[(size_t)NB * NS * ND];
__device__ float g_rowsum[(size_t)NB * NH * NS];

// ---------------- tf32 mma helpers ----------------
__device__ __forceinline__ uint32_t f2tf(float f) {
    uint32_t u;
    asm("cvt.rna.tf32.f32 %0, %1;" : "=r"(u) : "f"(f));
    return u;
}
__device__ __forceinline__ float uaf(uint32_t u) { return __uint_as_float(u); }
__device__ __forceinline__ uint32_t fau(float f) { return __float_as_uint(f); }

__device__ __forceinline__ void mma_tf32(float c[4], const uint32_t a[4], const uint32_t b[2]) {
    asm volatile(
        "mma.sync.aligned.m16n8k8.row.col.f32.tf32.tf32.f32 "
        "{%0,%1,%2,%3}, {%4,%5,%6,%7}, {%8,%9}, {%0,%1,%2,%3};"
        : "+f"(c[0]), "+f"(c[1]), "+f"(c[2]), "+f"(c[3])
        : "r"(a[0]), "r"(a[1]), "r"(a[2]), "r"(a[3]), "r"(b[0]), "r"(b[1]));
}

// ---------------------------------------------------------------------------
// Batched GEMM: C = A @ W^T + bias, tf32, double-buffered smem.
// M=4096, N=K=1024. BM=BN=128, BK=16, 256 threads, warp tile 32x64.
// SPLIT=1: out (b,h,s,dh), 3 problems via blockIdx.z; SPLIT=0: row-major.
// ---------------------------------------------------------------------------
#define GS 20
struct G3 {
    const float* A[3];
    const float* W[3];
    const float* B[3];
    float* O[3];
};

template <int SPLIT>
__global__ __launch_bounds__(256) void gemm_tf32(G3 p)
{
    __shared__ float As[2][128 * GS];
    __shared__ float Ws[2][128 * GS];

    const int z = SPLIT ? blockIdx.z : 0;
    const float* __restrict__ A = p.A[z];
    const float* __restrict__ W = p.W[z];
    const float* __restrict__ bias = p.B[z];
    float* __restrict__ out = p.O[z];

    const int tid = threadIdx.x;
    const int wid = tid >> 5, lane = tid & 31;
    const int g = lane >> 2, t = lane & 3;
    const int wm = (wid & 3) * 32;
    const int wn = (wid >> 2) * 64;
    const int bm = blockIdx.y * 128, bn = blockIdx.x * 128;

    const int lr = tid >> 1;
    const int lk = (tid & 1) * 8;

    float c[2][8][4];
#pragma unroll
    for (int i = 0; i < 2; i++)
#pragma unroll
        for (int j = 0; j < 8; j++)
#pragma unroll
            for (int q = 0; q < 4; q++) c[i][j][q] = 0.f;

    const float* aptr = A + (size_t)(bm + lr) * ND + lk;
    const float* wptr = W + (size_t)(bn + lr) * ND + lk;

    {
        float4 a0 = *(const float4*)(aptr);
        float4 a1 = *(const float4*)(aptr + 4);
        float4 w0 = *(const float4*)(wptr);
        float4 w1 = *(const float4*)(wptr + 4);
        *(float4*)&As[0][lr * GS + lk]     = make_float4(uaf(f2tf(a0.x)), uaf(f2tf(a0.y)), uaf(f2tf(a0.z)), uaf(f2tf(a0.w)));
        *(float4*)&As[0][lr * GS + lk + 4] = make_float4(uaf(f2tf(a1.x)), uaf(f2tf(a1.y)), uaf(f2tf(a1.z)), uaf(f2tf(a1.w)));
        *(float4*)&Ws[0][lr * GS + lk]     = make_float4(uaf(f2tf(w0.x)), uaf(f2tf(w0.y)), uaf(f2tf(w0.z)), uaf(f2tf(w0.w)));
        *(float4*)&Ws[0][lr * GS + lk + 4] = make_float4(uaf(f2tf(w1.x)), uaf(f2tf(w1.y)), uaf(f2tf(w1.z)), uaf(f2tf(w1.w)));
    }
    __syncthreads();

    for (int k0 = 0; k0 < ND; k0 += 16) {
        const int s = (k0 >> 4) & 1;
        const bool more = (k0 + 16) < ND;
        float4 a0, a1, w0, w1;
        if (more) {
            a0 = *(const float4*)(aptr + k0 + 16);
            a1 = *(const float4*)(aptr + k0 + 20);
            w0 = *(const float4*)(wptr + k0 + 16);
            w1 = *(const float4*)(wptr + k0 + 20);
        }

#pragma unroll
        for (int kk = 0; kk < 16; kk += 8) {
            uint32_t af[2][4];
#pragma unroll
            for (int mt = 0; mt < 2; mt++) {
                const int r = wm + mt * 16;
                af[mt][0] = fau(As[s][(r + g)     * GS + kk + t]);
                af[mt][1] = fau(As[s][(r + g + 8) * GS + kk + t]);
                af[mt][2] = fau(As[s][(r + g)     * GS + kk + t + 4]);
                af[mt][3] = fau(As[s][(r + g + 8) * GS + kk + t + 4]);
            }
#pragma unroll
            for (int nt = 0; nt < 8; nt++) {
                uint32_t bf[2];
                const int col = wn + nt * 8;
                bf[0] = fau(Ws[s][(col + g) * GS + kk + t]);
                bf[1] = fau(Ws[s][(col + g) * GS + kk + t + 4]);
                mma_tf32(c[0][nt], af[0], bf);
                mma_tf32(c[1][nt], af[1], bf);
            }
        }

        if (more) {
            const int d = s ^ 1;
            *(float4*)&As[d][lr * GS + lk]     = make_float4(uaf(f2tf(a0.x)), uaf(f2tf(a0.y)), uaf(f2tf(a0.z)), uaf(f2tf(a0.w)));
            *(float4*)&As[d][lr * GS + lk + 4] = make_float4(uaf(f2tf(a1.x)), uaf(f2tf(a1.y)), uaf(f2tf(a1.z)), uaf(f2tf(a1.w)));
            *(float4*)&Ws[d][lr * GS + lk]     = make_float4(uaf(f2tf(w0.x)), uaf(f2tf(w0.y)), uaf(f2tf(w0.z)), uaf(f2tf(w0.w)));
            *(float4*)&Ws[d][lr * GS + lk + 4] = make_float4(uaf(f2tf(w1.x)), uaf(f2tf(w1.y)), uaf(f2tf(w1.z)), uaf(f2tf(w1.w)));
            __syncthreads();
        }
    }

#pragma unroll
    for (int mt = 0; mt < 2; mt++) {
#pragma unroll
        for (int rr = 0; rr < 2; rr++) {
            const int m = bm + wm + mt * 16 + g + rr * 8;
            const int b = m >> 11, sIdx = m & (NS - 1);
#pragma unroll
            for (int nt = 0; nt < 8; nt++) {
                const int col = bn + wn + nt * 8 + 2 * t;
                float2 v;
                v.x = c[mt][nt][rr * 2 + 0] + bias[col];
                v.y = c[mt][nt][rr * 2 + 1] + bias[col + 1];
                if (SPLIT) {
                    const int h = col >> 6, dh = col & 63;
                    *(float2*)&out[((size_t)(b * NH + h) * NS + sIdx) * NDH + dh] = v;
                } else {
                    *(float2*)&out[(size_t)m * ND + col] = v;
                }
            }
        }
    }
}

// ---------------------------------------------------------------------------
// Attention v4: 128-thread blocks (4 warps), 64 q rows per block.
// Warp = 16 q rows x FULL 64 keys -> complete rowsums per warp, and the
// S-MMA output fragment is reused DIRECTLY as the PV A-fragment via a
// key-permuted V layout (pi = [0,2,4,6,1,3,5,7] per 8-key group):
//   e never touches smem. Per 8-key chunk: 8 S-MMAs -> exp -> weights STG
//   -> 8 PV-MMAs. Live lg/e = 4 regs; qf 32 + cacc 32 ~ 100 regs total.
// Smem: Ks 64x68 (Q staged here first, aliased), Vs 64x72 = 35,840 B.
// ---------------------------------------------------------------------------
__global__ __launch_bounds__(128) void attn_tf32(
    const int* __restrict__ mask, float* __restrict__ wout)
{
    __shared__ float Ks[64 * 68];
    __shared__ float Vs[64 * 72];

    const int b = blockIdx.z, h = blockIdx.y;
    const int q0 = blockIdx.x * 64;
    const int tid = threadIdx.x;
    const int wid = tid >> 5, lane = tid & 31;
    const int g = lane >> 2, t = lane & 3;
    const int wq = wid * 16;                 // warp's q-row base in block
    const size_t bh = (size_t)(b * NH + h);

    const int qr0 = q0 + wq + g;             // global q rows owned by thread
    const int qr1 = qr0 + 8;

    // Stage Q (64x64) into Ks (aliased), tf32
    const float* qptr = g_q + (bh * NS + q0) * NDH;
#pragma unroll
    for (int i = 0; i < 8; i++) {
        const int lin = tid + i * 128;
        const int r = lin >> 4, c4 = (lin & 15) * 4;
        float4 v = *(const float4*)(qptr + r * NDH + c4);
        *(float4*)&Ks[r * 68 + c4] =
            make_float4(uaf(f2tf(v.x)), uaf(f2tf(v.y)), uaf(f2tf(v.z)), uaf(f2tf(v.w)));
    }
    __syncthreads();

    // Q fragments: 8 k-chunks x 4 regs = 32 registers, resident all kernel
    uint32_t qf[8][4];
#pragma unroll
    for (int kd = 0; kd < 8; kd++) {
        qf[kd][0] = fau(Ks[(wq + g)     * 68 + kd * 8 + t]);
        qf[kd][1] = fau(Ks[(wq + g + 8) * 68 + kd * 8 + t]);
        qf[kd][2] = fau(Ks[(wq + g)     * 68 + kd * 8 + t + 4]);
        qf[kd][3] = fau(Ks[(wq + g + 8) * 68 + kd * 8 + t + 4]);
    }

    float cacc[8][4];
#pragma unroll
    for (int nd = 0; nd < 8; nd++)
#pragma unroll
        for (int q = 0; q < 4; q++) cacc[nd][q] = 0.f;
    float rs0 = 0.f, rs1 = 0.f;

    const int* mbase = mask + (size_t)b * NS * NS;
    float* wbase = wout ? wout + bh * NS * NS : nullptr;

    for (int kt = 0; kt < NS / 64; kt++) {
        __syncthreads();   // prev tile's reads done (covers qf build on kt=0)
        const float* kptr = g_k + (bh * NS + kt * 64) * NDH;
        const float* vptr = g_v + (bh * NS + kt * 64) * NDH;
#pragma unroll
        for (int i = 0; i < 8; i++) {
            const int lin = tid + i * 128;
            const int r = lin >> 4, c4 = (lin & 15) * 4;
            float4 kv = *(const float4*)(kptr + r * NDH + c4);
            float4 vv = *(const float4*)(vptr + r * NDH + c4);
            *(float4*)&Ks[r * 68 + c4] =
                make_float4(uaf(f2tf(kv.x)), uaf(f2tf(kv.y)), uaf(f2tf(kv.z)), uaf(f2tf(kv.w)));
            // V staged with per-8-group row permutation sigma(c) = 4*(c&1) + (c>>1)
            const int slot = (r & ~7) | (4 * (r & 1) + ((r & 7) >> 1));
            *(float4*)&Vs[slot * 72 + c4] =
                make_float4(uaf(f2tf(vv.x)), uaf(f2tf(vv.y)), uaf(f2tf(vv.z)), uaf(f2tf(vv.w)));
        }
        __syncthreads();

        // Per 8-key chunk: S-MMAs -> mask/exp -> weights STG -> PV-MMAs
#pragma unroll
        for (int kc = 0; kc < 8; kc++) {
            float lg[4] = {0.f, 0.f, 0.f, 0.f};
#pragma unroll
            for (int kd = 0; kd < 8; kd++) {
                uint32_t bf[2];
                bf[0] = fau(Ks[(kc * 8 + g) * 68 + kd * 8 + t]);
                bf[1] = fau(Ks[(kc * 8 + g) * 68 + kd * 8 + t + 4]);
                mma_tf32(lg, qf[kd], bf);
            }
            // c-layout: lg0=(qr0,col), lg1=(qr0,col+1), lg2=(qr1,col), lg3=(qr1,col+1)
            const int col = kt * 64 + kc * 8 + 2 * t;
            int2 m0 = *(const int2*)(mbase + (size_t)qr0 * NS + col);
            int2 m1 = *(const int2*)(mbase + (size_t)qr1 * NS + col);
            float e0 = m0.x ? 0.f : __expf(lg[0] * 0.125f);
            float e1 = m0.y ? 0.f : __expf(lg[1] * 0.125f);
            float e2 = m1.x ? 0.f : __expf(lg[2] * 0.125f);
            float e3 = m1.y ? 0.f : __expf(lg[3] * 0.125f);
            rs0 += e0 + e1;
            rs1 += e2 + e3;
            if (wbase) {
                *(float2*)&wbase[(size_t)qr0 * NS + col] = make_float2(e0, e1);
                *(float2*)&wbase[(size_t)qr1 * NS + col] = make_float2(e2, e3);
            }
            // A-frag for PV over permuted key slots: (e0, e2, e1, e3)
            uint32_t af[4] = { f2tf(e0), f2tf(e2), f2tf(e1), f2tf(e3) };
#pragma unroll
            for (int nd = 0; nd < 8; nd++) {
                uint32_t bf[2];
                bf[0] = fau(Vs[(kc * 8 + t)     * 72 + nd * 8 + g]);
                bf[1] = fau(Vs[(kc * 8 + t + 4) * 72 + nd * 8 + g]);
                mma_tf32(cacc[nd], af, bf);
            }
        }
    }

    // Rowsums: warp owns full rows; reduce over t within each quad
    rs0 += __shfl_xor_sync(0xffffffffu, rs0, 1);
    rs0 += __shfl_xor_sync(0xffffffffu, rs0, 2);
    rs1 += __shfl_xor_sync(0xffffffffu, rs1, 1);
    rs1 += __shfl_xor_sync(0xffffffffu, rs1, 2);
    if (t == 0) {
        g_rowsum[bh * NS + qr0] = rs0;
        g_rowsum[bh * NS + qr1] = rs1;
    }
    const float inv0 = 1.f / rs0, inv1 = 1.f / rs1;

    // Normalized attn, concat layout (b, s, h*64 + dh)
#pragma unroll
    for (int nd = 0; nd < 8; nd++) {
        const int dh = nd * 8 + 2 * t;
        *(float2*)&g_attn[((size_t)b * NS + qr0) * ND + h * NDH + dh] =
            make_float2(cacc[nd][0] * inv0, cacc[nd][1] * inv0);
        *(float2*)&g_attn[((size_t)b * NS + qr1) * ND + h * NDH + dh] =
            make_float2(cacc[nd][2] * inv1, cacc[nd][3] * inv1);
    }
}

// Scale each weights row by 1/rowsum
__global__ __launch_bounds__(128) void norm_w(float* __restrict__ w)
{
    const int row = blockIdx.x;
    const float inv = 1.f / g_rowsum[row];
    float4* p = (float4*)(w + (size_t)row * NS);
#pragma unroll
    for (int i = threadIdx.x; i < NS / 4; i += 128) {
        float4 v = p[i];
        v.x *= inv; v.y *= inv; v.z *= inv; v.w *= inv;
        p[i] = v;
    }
}

extern "C" void kernel_launch(void* const* d_in, const int* in_sizes, int n_in,
                              void* d_out, int out_size)
{
    const float* Xq  = (const float*)d_in[0];
    const float* Xk  = (const float*)d_in[1];
    const float* Xv  = (const float*)d_in[2];
    const int*   msk = (const int*)d_in[3];
    const float* Wq  = (const float*)d_in[4];
    const float* bq  = (const float*)d_in[5];
    const float* Wk  = (const float*)d_in[6];
    const float* bk  = (const float*)d_in[7];
    const float* Wv  = (const float*)d_in[8];
    const float* bv  = (const float*)d_in[9];
    const float* Wo  = (const float*)d_in[10];
    const float* bo  = (const float*)d_in[11];

    float* out = (float*)d_out;
    const size_t n_attn = (size_t)NB * NS * ND;
    const size_t n_w    = (size_t)NB * NH * NS * NS;

    float* attn_dst = nullptr;
    float* w_dst = nullptr;
    if ((size_t)out_size >= n_attn + n_w) { attn_dst = out; w_dst = out + n_attn; }
    else if ((size_t)out_size >= n_w)     { w_dst = out; }
    else                                  { attn_dst = out; }

    float *pq, *pk, *pv, *pa;
    cudaGetSymbolAddress((void**)&pq, g_q);
    cudaGetSymbolAddress((void**)&pk, g_k);
    cudaGetSymbolAddress((void**)&pv, g_v);
    cudaGetSymbolAddress((void**)&pa, g_attn);

    G3 pj;
    pj.A[0] = Xq; pj.W[0] = Wq; pj.B[0] = bq; pj.O[0] = pq;
    pj.A[1] = Xk; pj.W[1] = Wk; pj.B[1] = bk; pj.O[1] = pk;
    pj.A[2] = Xv; pj.W[2] = Wv; pj.B[2] = bv; pj.O[2] = pv;
    gemm_tf32<1><<<dim3(ND / 128, NM / 128, 3), 256>>>(pj);

    attn_tf32<<<dim3(NS / 64, NH, NB), 128>>>(msk, w_dst);

    if (w_dst) norm_w<<<NB * NH * NS, 128>>>(w_dst);

    if (attn_dst) {
        G3 po;
        po.A[0] = pa; po.W[0] = Wo; po.B[0] = bo; po.O[0] = attn_dst;
        po.A[1] = pa; po.W[1] = Wo; po.B[1] = bo; po.O[1] = attn_dst;
        po.A[2] = pa; po.W[2] = Wo; po.B[2] = bo; po.O[2] = attn_dst;
        gemm_tf32<0><<<dim3(ND / 128, NM / 128, 1), 256>>>(po);
    }
}